// round 1
// baseline (speedup 1.0000x reference)
#include <cuda_runtime.h>
#include <math.h>

// Problem dims (fixed by the reference)
namespace cfg {
constexpr int V = 32000, E = 512, H = 1024, S = 50, B = 64, T = 10;
constexpr int H2 = 2 * H, H3 = 3 * H;
}
using namespace cfg;

// ---------------- device scratch (no allocations allowed) ----------------
__device__ float g_xs[T * B * E];        // gathered embeddings  [T*B, E]
__device__ float g_gi[T * B * H3];       // x @ w_ih^T + b_ih    [T*B, 3H]
__device__ float g_gh[B * H3];           // h @ w_hh^T + b_hh    [B, 3H] (per step)
__device__ float g_hs[T * B * H];        // GRU hidden states    [T, B, H]
__device__ float g_keys[B * S * H2];     // enc_out transposed   [B, S, 2H]
__device__ float g_uk[B * S * H];        // keys @ ua_w^T + ua_b [B*S, H]
__device__ float g_wq[T * B * H];        // hs @ wa_w^T + wa_b   [T*B, H]
__device__ float g_sc[T * B * S];        // scores / weights     [T*B, S]

// ---------------- kernels ----------------

// xs[t*B+b][e] = emb[dec_in[b][t]][e],  dec_in = [SOS=0, target[:, :T-1]]
__global__ void k_gather(const int* __restrict__ target,
                         const float* __restrict__ emb,
                         float* __restrict__ xs) {
    int idx = blockIdx.x * 256 + threadIdx.x;
    if (idx >= T * B * E) return;
    int e = idx % E;
    int m = idx / E;
    int b = m % B;
    int t = m / B;
    int tok = (t == 0) ? 0 : target[b * T + (t - 1)];
    xs[idx] = emb[tok * E + e];
}

// keys[b][s][d] = enc_out[s][b][d]
__global__ void k_keys(const float* __restrict__ enc, float* __restrict__ keys) {
    int idx = blockIdx.x * 256 + threadIdx.x;
    if (idx >= B * S * H2) return;
    int d = idx % H2;
    int bs = idx / H2;
    int s = bs % S;
    int b = bs / S;
    keys[idx] = enc[(s * B + b) * H2 + d];
}

// C[m][n] = bias[n] + sum_k A[m][k] * W[n][k]
// Assumes M % 64 == 0, N % 64 == 0, K % 16 == 0 (true for all call sites).
__global__ void k_gemm(const float* __restrict__ A, const float* __restrict__ W,
                       const float* __restrict__ bias, float* __restrict__ C,
                       int M, int N, int K) {
    constexpr int BM = 64, BN = 64, BK = 16;
    __shared__ float As[BK][BM + 1];
    __shared__ float Bs[BK][BN + 1];
    const int tid = threadIdx.x;               // 256 threads
    const int bm = blockIdx.y * BM, bn = blockIdx.x * BN;
    const int tx = tid & 15, ty = tid >> 4;
    float acc[4][4] = {};

    for (int k0 = 0; k0 < K; k0 += BK) {
#pragma unroll
        for (int i = 0; i < 4; i++) {
            int idx = i * 256 + tid;
            int r = idx >> 4, c = idx & 15;
            As[c][r] = A[(bm + r) * K + k0 + c];
            Bs[c][r] = W[(bn + r) * K + k0 + c];
        }
        __syncthreads();
#pragma unroll
        for (int kk = 0; kk < BK; kk++) {
            float a[4], b[4];
#pragma unroll
            for (int i = 0; i < 4; i++) a[i] = As[kk][ty * 4 + i];
#pragma unroll
            for (int j = 0; j < 4; j++) b[j] = Bs[kk][tx * 4 + j];
#pragma unroll
            for (int i = 0; i < 4; i++)
#pragma unroll
                for (int j = 0; j < 4; j++)
                    acc[i][j] = fmaf(a[i], b[j], acc[i][j]);
        }
        __syncthreads();
    }
#pragma unroll
    for (int i = 0; i < 4; i++) {
        int m = bm + ty * 4 + i;
#pragma unroll
        for (int j = 0; j < 4; j++) {
            int n = bn + tx * 4 + j;
            C[m * N + n] = acc[i][j] + bias[n];
        }
    }
}

// GRU gate combine: h' = (1-z)*tanh(in + r*hn) + z*h
__global__ void k_gru(const float* __restrict__ gi, const float* __restrict__ gh,
                      const float* __restrict__ hprev, float* __restrict__ hnew) {
    int idx = blockIdx.x * 256 + threadIdx.x;
    if (idx >= B * H) return;
    int b = idx / H, j = idx % H;
    const float* gib = gi + b * H3;
    const float* ghb = gh + b * H3;
    float ir = gib[j], iz = gib[H + j], in_ = gib[2 * H + j];
    float hr = ghb[j], hz = ghb[H + j], hn = ghb[2 * H + j];
    float r = 1.f / (1.f + expf(-(ir + hr)));
    float z = 1.f / (1.f + expf(-(iz + hz)));
    float n = tanhf(in_ + r * hn);
    hnew[idx] = (1.f - z) * n + z * hprev[idx];
}

// scores[(t*B+b)*S + s] = va_b + sum_h va_w[h] * tanh(wq[t*B+b][h] + uk[b*S+s][h])
// one warp per (t,b,s)
__global__ void k_scores(const float* __restrict__ wq, const float* __restrict__ uk,
                         const float* __restrict__ va_w, const float* __restrict__ va_b,
                         float* __restrict__ scores) {
    int warp = (blockIdx.x * blockDim.x + threadIdx.x) >> 5;
    int lane = threadIdx.x & 31;
    if (warp >= T * B * S) return;
    int s = warp % S;
    int tb = warp / S;
    int b = tb % B;
    const float* wqr = wq + tb * H;
    const float* ukr = uk + (b * S + s) * H;
    float acc = 0.f;
    for (int h = lane; h < H; h += 32)
        acc = fmaf(va_w[h], tanhf(wqr[h] + ukr[h]), acc);
#pragma unroll
    for (int o = 16; o; o >>= 1) acc += __shfl_xor_sync(0xffffffffu, acc, o);
    if (lane == 0) scores[warp] = acc + va_b[0];
}

// softmax over S (=50) per row; one warp per (t,b)
__global__ void k_softmax(float* __restrict__ scores) {
    int row = (blockIdx.x * blockDim.x + threadIdx.x) >> 5;
    int lane = threadIdx.x & 31;
    if (row >= T * B) return;
    float* p = scores + row * S;
    float v0 = (lane < S) ? p[lane] : -1e30f;
    float v1 = (lane + 32 < S) ? p[lane + 32] : -1e30f;
    float m = fmaxf(v0, v1);
#pragma unroll
    for (int o = 16; o; o >>= 1) m = fmaxf(m, __shfl_xor_sync(0xffffffffu, m, o));
    float e0 = (lane < S) ? expf(v0 - m) : 0.f;
    float e1 = (lane + 32 < S) ? expf(v1 - m) : 0.f;
    float sum = e0 + e1;
#pragma unroll
    for (int o = 16; o; o >>= 1) sum += __shfl_xor_sync(0xffffffffu, sum, o);
    float inv = 1.f / sum;
    if (lane < S) p[lane] = e0 * inv;
    if (lane + 32 < S) p[lane + 32] = e1 * inv;
}

// context[b][t][:] = sum_s w[t,b,s] * keys[b,s,:]; then log_softmax over 2H.
// one block (256 threads) per (b,t); each thread owns 8 of the 2048 columns.
__global__ void k_context(const float* __restrict__ weights,
                          const float* __restrict__ keys,
                          float* __restrict__ out) {
    int b = blockIdx.x / T, t = blockIdx.x % T;
    __shared__ float w[S];
    __shared__ float red[8];
    int tid = threadIdx.x;
    if (tid < S) w[tid] = weights[(t * B + b) * S + tid];
    __syncthreads();

    float c[8];
#pragma unroll
    for (int i = 0; i < 8; i++) c[i] = 0.f;
    const float* kb = keys + b * S * H2;
    for (int s = 0; s < S; s++) {
        float ws = w[s];
        const float* kr = kb + s * H2;
#pragma unroll
        for (int i = 0; i < 8; i++) c[i] = fmaf(ws, kr[tid + i * 256], c[i]);
    }

    // block max
    float m = c[0];
#pragma unroll
    for (int i = 1; i < 8; i++) m = fmaxf(m, c[i]);
#pragma unroll
    for (int o = 16; o; o >>= 1) m = fmaxf(m, __shfl_xor_sync(0xffffffffu, m, o));
    if ((tid & 31) == 0) red[tid >> 5] = m;
    __syncthreads();
    if (tid == 0) {
        float mm = red[0];
        for (int i = 1; i < 8; i++) mm = fmaxf(mm, red[i]);
        red[0] = mm;
    }
    __syncthreads();
    m = red[0];
    __syncthreads();

    // block sum(exp)
    float sum = 0.f;
#pragma unroll
    for (int i = 0; i < 8; i++) sum += expf(c[i] - m);
#pragma unroll
    for (int o = 16; o; o >>= 1) sum += __shfl_xor_sync(0xffffffffu, sum, o);
    if ((tid & 31) == 0) red[tid >> 5] = sum;
    __syncthreads();
    if (tid == 0) {
        float ss = 0.f;
        for (int i = 0; i < 8; i++) ss += red[i];
        red[0] = ss;
    }
    __syncthreads();
    float lse = m + logf(red[0]);

    float* o_ = out + (b * T + t) * H2;
#pragma unroll
    for (int i = 0; i < 8; i++) o_[tid + i * 256] = c[i] - lse;
}

__global__ void k_hlast(const float* __restrict__ src, float* __restrict__ dst) {
    int idx = blockIdx.x * 256 + threadIdx.x;
    if (idx < B * H) dst[idx] = src[idx];
}

// ---------------- launch ----------------
extern "C" void kernel_launch(void* const* d_in, const int* in_sizes, int n_in,
                              void* d_out, int out_size) {
    const float* enc    = (const float*)d_in[0];
    const float* hidden = (const float*)d_in[1];
    const int*   target = (const int*)d_in[2];
    const float* emb    = (const float*)d_in[3];
    const float* w_ih   = (const float*)d_in[4];
    const float* w_hh   = (const float*)d_in[5];
    const float* b_ih   = (const float*)d_in[6];
    const float* b_hh   = (const float*)d_in[7];
    const float* wa_w   = (const float*)d_in[8];
    const float* wa_b   = (const float*)d_in[9];
    const float* ua_w   = (const float*)d_in[10];
    const float* ua_b   = (const float*)d_in[11];
    const float* va_w   = (const float*)d_in[12];
    const float* va_b   = (const float*)d_in[13];
    float* out = (float*)d_out;

    float *xs, *gi, *gh, *hs, *keys, *uk, *wq, *sc;
    cudaGetSymbolAddress((void**)&xs, g_xs);
    cudaGetSymbolAddress((void**)&gi, g_gi);
    cudaGetSymbolAddress((void**)&gh, g_gh);
    cudaGetSymbolAddress((void**)&hs, g_hs);
    cudaGetSymbolAddress((void**)&keys, g_keys);
    cudaGetSymbolAddress((void**)&uk, g_uk);
    cudaGetSymbolAddress((void**)&wq, g_wq);
    cudaGetSymbolAddress((void**)&sc, g_sc);

    // embedding gather + key transpose (independent)
    k_gather<<<(T * B * E + 255) / 256, 256>>>(target, emb, xs);
    k_keys<<<(B * S * H2 + 255) / 256, 256>>>(enc, keys);

    // gi = xs @ w_ih^T + b_ih   [640, 3072], K=512
    k_gemm<<<dim3(H3 / 64, (T * B) / 64), 256>>>(xs, w_ih, b_ih, gi, T * B, H3, E);

    // uk = keys @ ua_w^T + ua_b [3200, 1024], K=2048 (largest GEMM)
    k_gemm<<<dim3(H / 64, (B * S) / 64), 256>>>(keys, ua_w, ua_b, uk, B * S, H, H2);

    // sequential GRU over T steps
    const float* hprev = hidden;  // [B, H]
    for (int t = 0; t < T; t++) {
        k_gemm<<<dim3(H3 / 64, B / 64), 256>>>(hprev, w_hh, b_hh, gh, B, H3, H);
        k_gru<<<(B * H + 255) / 256, 256>>>(gi + t * B * H3, gh, hprev, hs + t * B * H);
        hprev = hs + t * B * H;
    }

    // wq = hs @ wa_w^T + wa_b   [640, 1024], K=1024
    k_gemm<<<dim3(H / 64, (T * B) / 64), 256>>>(hs, wa_w, wa_b, wq, T * B, H, H);

    // additive attention scores + softmax
    k_scores<<<(T * B * S * 32 + 255) / 256, 256>>>(wq, uk, va_w, va_b, sc);
    k_softmax<<<(T * B * 32 + 255) / 256, 256>>>(sc);

    // context + log_softmax into out[B, T, 2H]
    k_context<<<B * T, 256>>>(sc, keys, out);

    // h_last appended after out (tuple output flattened)
    if (out_size >= B * T * H2 + B * H)
        k_hlast<<<(B * H + 255) / 256, 256>>>(hs + (T - 1) * B * H, out + B * T * H2);
}

// round 2
// speedup vs baseline: 2.8238x; 2.8238x over previous
#include <cuda_runtime.h>
#include <math.h>

// Problem dims (fixed by the reference)
namespace cfg {
constexpr int V = 32000, E = 512, H = 1024, S = 50, B = 64, T = 10;
constexpr int H2 = 2 * H, H3 = 3 * H;
}
using namespace cfg;

// ---------------- device scratch (no allocations allowed) ----------------
__device__ float g_xs[T * B * E];        // gathered embeddings  [T*B, E]
__device__ float g_gi[T * B * H3];       // x @ w_ih^T + b_ih    [T*B, 3H]
__device__ float g_gh[B * H3];           // h @ w_hh^T + b_hh    [B, 3H] (per step)
__device__ float g_hs[T * B * H];        // GRU hidden states    [T, B, H]
__device__ float g_keys[B * S * H2];     // enc_out transposed   [B, S, 2H]
__device__ float g_uk[B * S * H];        // keys @ ua_w^T + ua_b [B*S, H]
__device__ float g_wq[T * B * H];        // hs @ wa_w^T + wa_b   [T*B, H]
__device__ float g_sc[T * B * S];        // scores / weights     [T*B, S]

// ---------------- small intrinsics ----------------
__device__ __forceinline__ unsigned f2tf32(float x) {
    unsigned u;
    asm("cvt.rna.tf32.f32 %0, %1;" : "=r"(u) : "f"(x));
    return u;
}
__device__ __forceinline__ float tanha(float x) {
    float y;
    asm("tanh.approx.f32 %0, %1;" : "=f"(y) : "f"(x));
    return y;
}
__device__ __forceinline__ void mma8(float* c, const unsigned* a, const unsigned* b) {
    asm volatile(
        "mma.sync.aligned.m16n8k8.row.col.f32.tf32.tf32.f32 "
        "{%0,%1,%2,%3}, {%4,%5,%6,%7}, {%8,%9}, {%0,%1,%2,%3};"
        : "+f"(c[0]), "+f"(c[1]), "+f"(c[2]), "+f"(c[3])
        : "r"(a[0]), "r"(a[1]), "r"(a[2]), "r"(a[3]), "r"(b[0]), "r"(b[1]));
}

// ---------------- tf32 tensor-core GEMM ----------------
// C[m][n] = bias[n] + sum_k A[m][k] * W[n][k]
// A: [M,K] row-major, W: [N,K] row-major. Requires M%BM==0, N%BN==0, K%32==0.
template <int BM, int BN, int WM, int WN>
__global__ void k_gemm_tf32(const float* __restrict__ A, const float* __restrict__ W,
                            const float* __restrict__ bias, float* __restrict__ C,
                            int M, int N, int K) {
    constexpr int BK = 32;
    constexpr int NT = WM * WN * 32;      // threads per block
    constexpr int TM = BM / WM;           // warp tile M
    constexpr int TN = BN / WN;           // warp tile N
    constexpr int MM = TM / 16;           // mma tiles per warp (m)
    constexpr int MN = TN / 8;            // mma tiles per warp (n)
    constexpr int LDSR = BK + 4;          // 36 floats: pad -> conflict-free frag loads
    constexpr int A_LD = BM * (BK / 4) / NT;  // float4 loads per thread (A)
    constexpr int B_LD = BN * (BK / 4) / NT;

    __shared__ unsigned As[BM * LDSR];
    __shared__ unsigned Bs[BN * LDSR];

    const int tid = threadIdx.x;
    const int warp = tid >> 5, lane = tid & 31;
    const int wm = warp / WN, wn = warp % WN;
    const int g = lane >> 2, tg = lane & 3;
    const int bm = blockIdx.y * BM, bn = blockIdx.x * BN;

    float acc[MM][MN][4];
#pragma unroll
    for (int im = 0; im < MM; im++)
#pragma unroll
        for (int in = 0; in < MN; in++)
#pragma unroll
            for (int q = 0; q < 4; q++) acc[im][in][q] = 0.f;

    float4 pa[A_LD], pb[B_LD];

    auto ld_tile = [&](int k0) {
#pragma unroll
        for (int i = 0; i < A_LD; i++) {
            int idx = tid + i * NT;
            int r = idx >> 3, kq = idx & 7;
            pa[i] = *(const float4*)(A + (size_t)(bm + r) * K + k0 + kq * 4);
        }
#pragma unroll
        for (int i = 0; i < B_LD; i++) {
            int idx = tid + i * NT;
            int r = idx >> 3, kq = idx & 7;
            pb[i] = *(const float4*)(W + (size_t)(bn + r) * K + k0 + kq * 4);
        }
    };
    auto st_tile = [&]() {
#pragma unroll
        for (int i = 0; i < A_LD; i++) {
            int idx = tid + i * NT;
            int r = idx >> 3, kq = idx & 7;
            uint4 v = make_uint4(f2tf32(pa[i].x), f2tf32(pa[i].y),
                                 f2tf32(pa[i].z), f2tf32(pa[i].w));
            *(uint4*)&As[r * LDSR + kq * 4] = v;
        }
#pragma unroll
        for (int i = 0; i < B_LD; i++) {
            int idx = tid + i * NT;
            int r = idx >> 3, kq = idx & 7;
            uint4 v = make_uint4(f2tf32(pb[i].x), f2tf32(pb[i].y),
                                 f2tf32(pb[i].z), f2tf32(pb[i].w));
            *(uint4*)&Bs[r * LDSR + kq * 4] = v;
        }
    };

    ld_tile(0);
    st_tile();
    __syncthreads();

    for (int k0 = 0; k0 < K; k0 += BK) {
        const bool has_next = (k0 + BK) < K;
        if (has_next) ld_tile(k0 + BK);

#pragma unroll
        for (int ks = 0; ks < 4; ks++) {
            const int kk = ks * 8;
            unsigned af[MM][4], bf[MN][2];
#pragma unroll
            for (int im = 0; im < MM; im++) {
                int m0 = wm * TM + im * 16;
                af[im][0] = As[(m0 + g) * LDSR + kk + tg];
                af[im][1] = As[(m0 + 8 + g) * LDSR + kk + tg];
                af[im][2] = As[(m0 + g) * LDSR + kk + 4 + tg];
                af[im][3] = As[(m0 + 8 + g) * LDSR + kk + 4 + tg];
            }
#pragma unroll
            for (int in = 0; in < MN; in++) {
                int n0 = wn * TN + in * 8;
                bf[in][0] = Bs[(n0 + g) * LDSR + kk + tg];
                bf[in][1] = Bs[(n0 + g) * LDSR + kk + 4 + tg];
            }
#pragma unroll
            for (int im = 0; im < MM; im++)
#pragma unroll
                for (int in = 0; in < MN; in++)
                    mma8(acc[im][in], af[im], bf[in]);
        }
        __syncthreads();
        if (has_next) {
            st_tile();
            __syncthreads();
        }
    }

    // epilogue: + bias, write
#pragma unroll
    for (int im = 0; im < MM; im++) {
        int row0 = bm + wm * TM + im * 16 + g;
#pragma unroll
        for (int in = 0; in < MN; in++) {
            int col = bn + wn * TN + in * 8 + 2 * tg;
            float2 bb = *(const float2*)(bias + col);
            float* c = acc[im][in];
            *(float2*)(C + (size_t)row0 * N + col) =
                make_float2(c[0] + bb.x, c[1] + bb.y);
            *(float2*)(C + (size_t)(row0 + 8) * N + col) =
                make_float2(c[2] + bb.x, c[3] + bb.y);
        }
    }
}

// ---------------- elementwise / attention kernels ----------------

// xs[t*B+b][e] = emb[dec_in[b][t]][e],  dec_in = [SOS=0, target[:, :T-1]]
__global__ void k_gather(const int* __restrict__ target,
                         const float* __restrict__ emb,
                         float* __restrict__ xs) {
    int idx = blockIdx.x * 256 + threadIdx.x;
    if (idx >= T * B * E) return;
    int e = idx % E;
    int m = idx / E;
    int b = m % B;
    int t = m / B;
    int tok = (t == 0) ? 0 : target[b * T + (t - 1)];
    xs[idx] = emb[tok * E + e];
}

// keys[b][s][d] = enc_out[s][b][d]
__global__ void k_keys(const float* __restrict__ enc, float* __restrict__ keys) {
    int idx = blockIdx.x * 256 + threadIdx.x;
    if (idx >= B * S * H2) return;
    int d = idx % H2;
    int bs = idx / H2;
    int s = bs % S;
    int b = bs / S;
    keys[idx] = enc[(s * B + b) * H2 + d];
}

// GRU gate combine: h' = (1-z)*tanh(in + r*hn) + z*h   (accurate math; protects h_last)
__global__ void k_gru(const float* __restrict__ gi, const float* __restrict__ gh,
                      const float* __restrict__ hprev, float* __restrict__ hnew) {
    int idx = blockIdx.x * 256 + threadIdx.x;
    if (idx >= B * H) return;
    int b = idx / H, j = idx % H;
    const float* gib = gi + b * H3;
    const float* ghb = gh + b * H3;
    float ir = gib[j], iz = gib[H + j], in_ = gib[2 * H + j];
    float hr = ghb[j], hz = ghb[H + j], hn = ghb[2 * H + j];
    float r = 1.f / (1.f + expf(-(ir + hr)));
    float z = 1.f / (1.f + expf(-(iz + hz)));
    float n = tanhf(in_ + r * hn);
    hnew[idx] = (1.f - z) * n + z * hprev[idx];
}

// scores: one warp per (t,b,s); float4 loads; HW tanh.approx
__global__ void k_scores(const float* __restrict__ wq, const float* __restrict__ uk,
                         const float* __restrict__ va_w, const float* __restrict__ va_b,
                         float* __restrict__ scores) {
    int warp = (blockIdx.x * blockDim.x + threadIdx.x) >> 5;
    int lane = threadIdx.x & 31;
    if (warp >= T * B * S) return;
    int s = warp % S;
    int tb = warp / S;
    int b = tb % B;
    const float4* wqr = (const float4*)(wq + tb * H);
    const float4* ukr = (const float4*)(uk + (b * S + s) * H);
    const float4* vw = (const float4*)va_w;
    float acc = 0.f;
#pragma unroll
    for (int i = 0; i < H / 128; i++) {
        float4 q = wqr[lane + i * 32];
        float4 u = ukr[lane + i * 32];
        float4 v = vw[lane + i * 32];
        acc = fmaf(v.x, tanha(q.x + u.x), acc);
        acc = fmaf(v.y, tanha(q.y + u.y), acc);
        acc = fmaf(v.z, tanha(q.z + u.z), acc);
        acc = fmaf(v.w, tanha(q.w + u.w), acc);
    }
#pragma unroll
    for (int o = 16; o; o >>= 1) acc += __shfl_xor_sync(0xffffffffu, acc, o);
    if (lane == 0) scores[warp] = acc + va_b[0];
}

// softmax over S (=50) per row; one warp per (t,b)
__global__ void k_softmax(float* __restrict__ scores) {
    int row = (blockIdx.x * blockDim.x + threadIdx.x) >> 5;
    int lane = threadIdx.x & 31;
    if (row >= T * B) return;
    float* p = scores + row * S;
    float v0 = (lane < S) ? p[lane] : -1e30f;
    float v1 = (lane + 32 < S) ? p[lane + 32] : -1e30f;
    float m = fmaxf(v0, v1);
#pragma unroll
    for (int o = 16; o; o >>= 1) m = fmaxf(m, __shfl_xor_sync(0xffffffffu, m, o));
    float e0 = (lane < S) ? expf(v0 - m) : 0.f;
    float e1 = (lane + 32 < S) ? expf(v1 - m) : 0.f;
    float sum = e0 + e1;
#pragma unroll
    for (int o = 16; o; o >>= 1) sum += __shfl_xor_sync(0xffffffffu, sum, o);
    float inv = 1.f / sum;
    if (lane < S) p[lane] = e0 * inv;
    if (lane + 32 < S) p[lane + 32] = e1 * inv;
}

// context + log_softmax: one block per b, all T accumulated while streaming keys once.
// 256 threads, thread owns 8 consecutive columns (2 float4s) of 2048.
__global__ void k_context(const float* __restrict__ weights,
                          const float* __restrict__ keys,
                          float* __restrict__ out) {
    int b = blockIdx.x;
    int tid = threadIdx.x;
    __shared__ float w[T][S];
    __shared__ float red[8];

    for (int i = tid; i < T * S; i += 256) {
        int t = i / S, s = i % S;
        w[t][s] = weights[(t * B + b) * S + s];
    }
    __syncthreads();

    float c[T][8];
#pragma unroll
    for (int t = 0; t < T; t++)
#pragma unroll
        for (int i = 0; i < 8; i++) c[t][i] = 0.f;

    const float* kb = keys + b * S * H2;
    for (int s = 0; s < S; s++) {
        float4 k0 = *(const float4*)(kb + s * H2 + tid * 8);
        float4 k1 = *(const float4*)(kb + s * H2 + tid * 8 + 4);
        float kv[8] = {k0.x, k0.y, k0.z, k0.w, k1.x, k1.y, k1.z, k1.w};
#pragma unroll
        for (int t = 0; t < T; t++) {
            float ws = w[t][s];
#pragma unroll
            for (int i = 0; i < 8; i++) c[t][i] = fmaf(ws, kv[i], c[t][i]);
        }
    }

    for (int t = 0; t < T; t++) {
        // block max
        float m = c[t][0];
#pragma unroll
        for (int i = 1; i < 8; i++) m = fmaxf(m, c[t][i]);
#pragma unroll
        for (int o = 16; o; o >>= 1) m = fmaxf(m, __shfl_xor_sync(0xffffffffu, m, o));
        if ((tid & 31) == 0) red[tid >> 5] = m;
        __syncthreads();
        if (tid == 0) {
            float mm = red[0];
            for (int i = 1; i < 8; i++) mm = fmaxf(mm, red[i]);
            red[0] = mm;
        }
        __syncthreads();
        m = red[0];
        __syncthreads();

        float sum = 0.f;
#pragma unroll
        for (int i = 0; i < 8; i++) sum += expf(c[t][i] - m);
#pragma unroll
        for (int o = 16; o; o >>= 1) sum += __shfl_xor_sync(0xffffffffu, sum, o);
        if ((tid & 31) == 0) red[tid >> 5] = sum;
        __syncthreads();
        if (tid == 0) {
            float ss = 0.f;
            for (int i = 1; i < 8; i++) ss += red[i];
            red[0] += ss;
        }
        __syncthreads();
        float lse = m + logf(red[0]);
        __syncthreads();

        float* o_ = out + (size_t)(b * T + t) * H2 + tid * 8;
        float4 o0 = make_float4(c[t][0] - lse, c[t][1] - lse, c[t][2] - lse, c[t][3] - lse);
        float4 o1 = make_float4(c[t][4] - lse, c[t][5] - lse, c[t][6] - lse, c[t][7] - lse);
        *(float4*)o_ = o0;
        *(float4*)(o_ + 4) = o1;
    }
}

__global__ void k_hlast(const float* __restrict__ src, float* __restrict__ dst) {
    int idx = blockIdx.x * 256 + threadIdx.x;
    if (idx < B * H) dst[idx] = src[idx];
}

// ---------------- launch ----------------
extern "C" void kernel_launch(void* const* d_in, const int* in_sizes, int n_in,
                              void* d_out, int out_size) {
    const float* enc    = (const float*)d_in[0];
    const float* hidden = (const float*)d_in[1];
    const int*   target = (const int*)d_in[2];
    const float* emb    = (const float*)d_in[3];
    const float* w_ih   = (const float*)d_in[4];
    const float* w_hh   = (const float*)d_in[5];
    const float* b_ih   = (const float*)d_in[6];
    const float* b_hh   = (const float*)d_in[7];
    const float* wa_w   = (const float*)d_in[8];
    const float* wa_b   = (const float*)d_in[9];
    const float* ua_w   = (const float*)d_in[10];
    const float* ua_b   = (const float*)d_in[11];
    const float* va_w   = (const float*)d_in[12];
    const float* va_b   = (const float*)d_in[13];
    float* out = (float*)d_out;

    float *xs, *gi, *gh, *hs, *keys, *uk, *wq, *sc;
    cudaGetSymbolAddress((void**)&xs, g_xs);
    cudaGetSymbolAddress((void**)&gi, g_gi);
    cudaGetSymbolAddress((void**)&gh, g_gh);
    cudaGetSymbolAddress((void**)&hs, g_hs);
    cudaGetSymbolAddress((void**)&keys, g_keys);
    cudaGetSymbolAddress((void**)&uk, g_uk);
    cudaGetSymbolAddress((void**)&wq, g_wq);
    cudaGetSymbolAddress((void**)&sc, g_sc);

    // embedding gather + key transpose (independent)
    k_gather<<<(T * B * E + 255) / 256, 256>>>(target, emb, xs);
    k_keys<<<(B * S * H2 + 255) / 256, 256>>>(enc, keys);

    // gi = xs @ w_ih^T + b_ih   [640, 3072], K=512
    k_gemm_tf32<128, 128, 4, 2><<<dim3(H3 / 128, (T * B) / 128), 256>>>(
        xs, w_ih, b_ih, gi, T * B, H3, E);

    // uk = keys @ ua_w^T + ua_b [3200, 1024], K=2048 (largest GEMM)
    k_gemm_tf32<128, 128, 4, 2><<<dim3(H / 128, (B * S) / 128), 256>>>(
        keys, ua_w, ua_b, uk, B * S, H, H2);

    // sequential GRU over T steps
    const float* hprev = hidden;  // [B, H]
    for (int t = 0; t < T; t++) {
        k_gemm_tf32<64, 128, 2, 4><<<dim3(H3 / 128, 1), 256>>>(
            hprev, w_hh, b_hh, gh, B, H3, H);
        k_gru<<<(B * H + 255) / 256, 256>>>(gi + t * B * H3, gh, hprev, hs + t * B * H);
        hprev = hs + t * B * H;
    }

    // wq = hs @ wa_w^T + wa_b   [640, 1024], K=1024
    k_gemm_tf32<128, 128, 4, 2><<<dim3(H / 128, (T * B) / 128), 256>>>(
        hs, wa_w, wa_b, wq, T * B, H, H);

    // additive attention scores + softmax
    k_scores<<<(T * B * S * 32 + 255) / 256, 256>>>(wq, uk, va_w, va_b, sc);
    k_softmax<<<(T * B * 32 + 255) / 256, 256>>>(sc);

    // context + log_softmax into out[B, T, 2H]
    k_context<<<B, 256>>>(sc, keys, out);

    // h_last appended after out (tuple output flattened)
    if (out_size >= B * T * H2 + B * H)
        k_hlast<<<(B * H + 255) / 256, 256>>>(hs + (T - 1) * B * H, out + B * T * H2);
}

// round 4
// speedup vs baseline: 3.9906x; 1.4132x over previous
#include <cuda_runtime.h>
#include <math.h>

// Problem dims (fixed by the reference)
namespace cfg {
constexpr int V = 32000, E = 512, H = 1024, S = 50, B = 64, T = 10;
constexpr int H2 = 2 * H, H3 = 3 * H;
constexpr int KSPLIT = 8;  // split-K factor for GRU gh GEMM
}
using namespace cfg;

// ---------------- device scratch (no allocations allowed) ----------------
__device__ float g_xs[T * B * E];          // gathered embeddings  [T*B, E]
__device__ float g_gi[T * B * H3];         // x @ w_ih^T + b_ih    [T*B, 3H]
__device__ float g_ghp[KSPLIT * B * H3];   // split-K partials of h @ w_hh^T
__device__ float g_hs[T * B * H];          // GRU hidden states    [T, B, H]
__device__ float g_keys[B * S * H2];       // enc_out transposed   [B, S, 2H]
__device__ float g_uk[B * S * H];          // keys @ ua_w^T + ua_b [B*S, H]
__device__ float g_wq[T * B * H];          // hs @ wa_w^T + wa_b   [T*B, H]
__device__ float g_sc[T * B * S];          // scores / weights     [T*B, S]

// ---------------- small intrinsics ----------------
__device__ __forceinline__ unsigned f2tf32(float x) {
    unsigned u;
    asm("cvt.rna.tf32.f32 %0, %1;" : "=r"(u) : "f"(x));
    return u;
}
__device__ __forceinline__ float tanha(float x) {
    float y;
    asm("tanh.approx.f32 %0, %1;" : "=f"(y) : "f"(x));
    return y;
}
__device__ __forceinline__ void mma8(float* c, const unsigned* a, const unsigned* b) {
    asm volatile(
        "mma.sync.aligned.m16n8k8.row.col.f32.tf32.tf32.f32 "
        "{%0,%1,%2,%3}, {%4,%5,%6,%7}, {%8,%9}, {%0,%1,%2,%3};"
        : "+f"(c[0]), "+f"(c[1]), "+f"(c[2]), "+f"(c[3])
        : "r"(a[0]), "r"(a[1]), "r"(a[2]), "r"(a[3]), "r"(b[0]), "r"(b[1]));
}

// ---------------- tf32 tensor-core GEMM (register-staged, PROVEN body) -----
// C[m][n] = (bias?bias[n]:0) + sum_{k in [z*klen, z*klen+klen)} A[m][k]*W[n][k]
// A: [M,K] row-major, W: [N,K] row-major. blockIdx.z selects K split; output
// written to C + z*M*N. Requires M%BM==0, N%BN==0, klen%32==0.
template <int BM, int BN, int WM, int WN>
__global__ void k_gemm_tf32(const float* __restrict__ A, const float* __restrict__ W,
                            const float* __restrict__ bias, float* __restrict__ C,
                            int M, int N, int K, int klen) {
    constexpr int BK = 32;
    constexpr int NT = WM * WN * 32;      // threads per block
    constexpr int TM = BM / WM;           // warp tile M
    constexpr int TN = BN / WN;           // warp tile N
    constexpr int MM = TM / 16;           // mma tiles per warp (m)
    constexpr int MN = TN / 8;            // mma tiles per warp (n)
    constexpr int LDSR = BK + 4;          // pad -> conflict-free frag loads
    constexpr int A_LD = BM * (BK / 4) / NT;
    constexpr int B_LD = BN * (BK / 4) / NT;

    __shared__ unsigned As[BM * LDSR];
    __shared__ unsigned Bs[BN * LDSR];

    const int tid = threadIdx.x;
    const int warp = tid >> 5, lane = tid & 31;
    const int wm = warp / WN, wn = warp % WN;
    const int g = lane >> 2, tg = lane & 3;
    const int bm = blockIdx.y * BM, bn = blockIdx.x * BN;
    const int kstart = blockIdx.z * klen;
    C += (size_t)blockIdx.z * M * N;

    float acc[MM][MN][4];
#pragma unroll
    for (int im = 0; im < MM; im++)
#pragma unroll
        for (int in = 0; in < MN; in++)
#pragma unroll
            for (int q = 0; q < 4; q++) acc[im][in][q] = 0.f;

    float4 pa[A_LD], pb[B_LD];

    auto ld_tile = [&](int k0) {
#pragma unroll
        for (int i = 0; i < A_LD; i++) {
            int idx = tid + i * NT;
            int r = idx >> 3, kq = idx & 7;
            pa[i] = *(const float4*)(A + (size_t)(bm + r) * K + kstart + k0 + kq * 4);
        }
#pragma unroll
        for (int i = 0; i < B_LD; i++) {
            int idx = tid + i * NT;
            int r = idx >> 3, kq = idx & 7;
            pb[i] = *(const float4*)(W + (size_t)(bn + r) * K + kstart + k0 + kq * 4);
        }
    };
    auto st_tile = [&]() {
#pragma unroll
        for (int i = 0; i < A_LD; i++) {
            int idx = tid + i * NT;
            int r = idx >> 3, kq = idx & 7;
            uint4 v = make_uint4(f2tf32(pa[i].x), f2tf32(pa[i].y),
                                 f2tf32(pa[i].z), f2tf32(pa[i].w));
            *(uint4*)&As[r * LDSR + kq * 4] = v;
        }
#pragma unroll
        for (int i = 0; i < B_LD; i++) {
            int idx = tid + i * NT;
            int r = idx >> 3, kq = idx & 7;
            uint4 v = make_uint4(f2tf32(pb[i].x), f2tf32(pb[i].y),
                                 f2tf32(pb[i].z), f2tf32(pb[i].w));
            *(uint4*)&Bs[r * LDSR + kq * 4] = v;
        }
    };

    ld_tile(0);
    st_tile();
    __syncthreads();

    for (int k0 = 0; k0 < klen; k0 += BK) {
        const bool has_next = (k0 + BK) < klen;
        if (has_next) ld_tile(k0 + BK);

#pragma unroll
        for (int ks = 0; ks < 4; ks++) {
            const int kk = ks * 8;
            unsigned af[MM][4], bf[MN][2];
#pragma unroll
            for (int im = 0; im < MM; im++) {
                int m0 = wm * TM + im * 16;
                af[im][0] = As[(m0 + g) * LDSR + kk + tg];
                af[im][1] = As[(m0 + 8 + g) * LDSR + kk + tg];
                af[im][2] = As[(m0 + g) * LDSR + kk + 4 + tg];
                af[im][3] = As[(m0 + 8 + g) * LDSR + kk + 4 + tg];
            }
#pragma unroll
            for (int in = 0; in < MN; in++) {
                int n0 = wn * TN + in * 8;
                bf[in][0] = Bs[(n0 + g) * LDSR + kk + tg];
                bf[in][1] = Bs[(n0 + g) * LDSR + kk + 4 + tg];
            }
#pragma unroll
            for (int im = 0; im < MM; im++)
#pragma unroll
                for (int in = 0; in < MN; in++)
                    mma8(acc[im][in], af[im], bf[in]);
        }
        __syncthreads();
        if (has_next) {
            st_tile();
            __syncthreads();
        }
    }

    // epilogue: + bias (optional), write
#pragma unroll
    for (int im = 0; im < MM; im++) {
        int row0 = bm + wm * TM + im * 16 + g;
#pragma unroll
        for (int in = 0; in < MN; in++) {
            int col = bn + wn * TN + in * 8 + 2 * tg;
            float bx = 0.f, by = 0.f;
            if (bias) {
                float2 bb = *(const float2*)(bias + col);
                bx = bb.x; by = bb.y;
            }
            float* c = acc[im][in];
            *(float2*)(C + (size_t)row0 * N + col) = make_float2(c[0] + bx, c[1] + by);
            *(float2*)(C + (size_t)(row0 + 8) * N + col) = make_float2(c[2] + bx, c[3] + by);
        }
    }
}

// ---------------- elementwise / attention kernels ----------------

__global__ void k_gather(const int* __restrict__ target,
                         const float* __restrict__ emb,
                         float* __restrict__ xs) {
    int idx = blockIdx.x * 256 + threadIdx.x;
    if (idx >= T * B * E) return;
    int e = idx % E;
    int m = idx / E;
    int b = m % B;
    int t = m / B;
    int tok = (t == 0) ? 0 : target[b * T + (t - 1)];
    xs[idx] = emb[tok * E + e];
}

__global__ void k_keys(const float* __restrict__ enc, float* __restrict__ keys) {
    int idx = blockIdx.x * 256 + threadIdx.x;
    if (idx >= B * S * H2) return;
    int d = idx % H2;
    int bs = idx / H2;
    int s = bs % S;
    int b = bs / S;
    keys[idx] = enc[(s * B + b) * H2 + d];
}

// reduce split-K partials of gh, add biases, apply GRU gates (accurate math).
__global__ void k_gru_red(const float* __restrict__ part, const float* __restrict__ gi,
                          const float* __restrict__ b_hh_, const float* __restrict__ hprev,
                          float* __restrict__ hnew) {
    int idx = blockIdx.x * 256 + threadIdx.x;
    if (idx >= B * H) return;
    int b = idx / H, j = idx % H;
    float hr = b_hh_[j], hz = b_hh_[H + j], hn = b_hh_[2 * H + j];
#pragma unroll
    for (int s = 0; s < KSPLIT; s++) {
        const float* p = part + (size_t)s * B * H3 + (size_t)b * H3;
        hr += p[j];
        hz += p[H + j];
        hn += p[2 * H + j];
    }
    const float* gib = gi + (size_t)b * H3;
    float ir = gib[j], iz = gib[H + j], in_ = gib[2 * H + j];
    float r = 1.f / (1.f + expf(-(ir + hr)));
    float z = 1.f / (1.f + expf(-(iz + hz)));
    float n = tanhf(in_ + r * hn);
    hnew[idx] = (1.f - z) * n + z * hprev[idx];
}

// scores: grid (B, 4); wq[T][H] staged in smem; each warp owns source positions.
__global__ void k_scores(const float* __restrict__ wq, const float* __restrict__ uk,
                         const float* __restrict__ va_w, const float* __restrict__ va_b,
                         float* __restrict__ scores) {
    __shared__ float wqs[T][H];  // 40 KB
    int b = blockIdx.x, q = blockIdx.y;
    int tid = threadIdx.x;
    for (int i = tid; i < T * H; i += 256) {
        wqs[0][i] = wq[(size_t)(i / H * B + b) * H + (i % H)];
    }
    __syncthreads();

    int warp = tid >> 5, lane = tid & 31;
    float vb = va_b[0];
    for (int s = q * 8 + warp; s < S; s += 32) {
        const float4* ukr = (const float4*)(uk + (size_t)(b * S + s) * H);
        const float4* vw = (const float4*)va_w;
        float acc[T];
#pragma unroll
        for (int t = 0; t < T; t++) acc[t] = 0.f;
#pragma unroll
        for (int i = 0; i < H / 128; i++) {
            float4 u = ukr[lane + i * 32];
            float4 v = vw[lane + i * 32];
#pragma unroll
            for (int t = 0; t < T; t++) {
                float4 w = *(const float4*)&wqs[t][(lane + i * 32) * 4];
                float a = acc[t];
                a = fmaf(v.x, tanha(w.x + u.x), a);
                a = fmaf(v.y, tanha(w.y + u.y), a);
                a = fmaf(v.z, tanha(w.z + u.z), a);
                a = fmaf(v.w, tanha(w.w + u.w), a);
                acc[t] = a;
            }
        }
#pragma unroll
        for (int t = 0; t < T; t++) {
#pragma unroll
            for (int o = 16; o; o >>= 1) acc[t] += __shfl_xor_sync(0xffffffffu, acc[t], o);
            if (lane == 0) scores[(size_t)(t * B + b) * S + s] = acc[t] + vb;
        }
    }
}

// softmax over S (=50) per row; one warp per (t,b)
__global__ void k_softmax(float* __restrict__ scores) {
    int row = (blockIdx.x * blockDim.x + threadIdx.x) >> 5;
    int lane = threadIdx.x & 31;
    if (row >= T * B) return;
    float* p = scores + (size_t)row * S;
    float v0 = (lane < S) ? p[lane] : -1e30f;
    float v1 = (lane + 32 < S) ? p[lane + 32] : -1e30f;
    float m = fmaxf(v0, v1);
#pragma unroll
    for (int o = 16; o; o >>= 1) m = fmaxf(m, __shfl_xor_sync(0xffffffffu, m, o));
    float e0 = (lane < S) ? expf(v0 - m) : 0.f;
    float e1 = (lane + 32 < S) ? expf(v1 - m) : 0.f;
    float sum = e0 + e1;
#pragma unroll
    for (int o = 16; o; o >>= 1) sum += __shfl_xor_sync(0xffffffffu, sum, o);
    float inv = 1.f / sum;
    if (lane < S) p[lane] = e0 * inv;
    if (lane + 32 < S) p[lane + 32] = e1 * inv;
}

// context + log_softmax: one block per b; keys[b] streamed once for all T.
__global__ void k_context(const float* __restrict__ weights,
                          const float* __restrict__ keys,
                          float* __restrict__ out) {
    int b = blockIdx.x;
    int tid = threadIdx.x;
    __shared__ float w[T][S];
    __shared__ float red[8];

    for (int i = tid; i < T * S; i += 256) {
        int t = i / S, s = i % S;
        w[t][s] = weights[(size_t)(t * B + b) * S + s];
    }
    __syncthreads();

    float c[T][8];
#pragma unroll
    for (int t = 0; t < T; t++)
#pragma unroll
        for (int i = 0; i < 8; i++) c[t][i] = 0.f;

    const float* kb = keys + (size_t)b * S * H2;
    for (int s = 0; s < S; s++) {
        float4 k0 = *(const float4*)(kb + s * H2 + tid * 8);
        float4 k1 = *(const float4*)(kb + s * H2 + tid * 8 + 4);
        float kv[8] = {k0.x, k0.y, k0.z, k0.w, k1.x, k1.y, k1.z, k1.w};
#pragma unroll
        for (int t = 0; t < T; t++) {
            float ws = w[t][s];
#pragma unroll
            for (int i = 0; i < 8; i++) c[t][i] = fmaf(ws, kv[i], c[t][i]);
        }
    }

    for (int t = 0; t < T; t++) {
        float m = c[t][0];
#pragma unroll
        for (int i = 1; i < 8; i++) m = fmaxf(m, c[t][i]);
#pragma unroll
        for (int o = 16; o; o >>= 1) m = fmaxf(m, __shfl_xor_sync(0xffffffffu, m, o));
        if ((tid & 31) == 0) red[tid >> 5] = m;
        __syncthreads();
        if (tid == 0) {
            float mm = red[0];
            for (int i = 1; i < 8; i++) mm = fmaxf(mm, red[i]);
            red[0] = mm;
        }
        __syncthreads();
        m = red[0];
        __syncthreads();

        float sum = 0.f;
#pragma unroll
        for (int i = 0; i < 8; i++) sum += expf(c[t][i] - m);
#pragma unroll
        for (int o = 16; o; o >>= 1) sum += __shfl_xor_sync(0xffffffffu, sum, o);
        if ((tid & 31) == 0) red[tid >> 5] = sum;
        __syncthreads();
        if (tid == 0) {
            float ss = 0.f;
            for (int i = 1; i < 8; i++) ss += red[i];
            red[0] += ss;
        }
        __syncthreads();
        float lse = m + logf(red[0]);
        __syncthreads();

        float* o_ = out + (size_t)(b * T + t) * H2 + tid * 8;
        *(float4*)o_ = make_float4(c[t][0] - lse, c[t][1] - lse, c[t][2] - lse, c[t][3] - lse);
        *(float4*)(o_ + 4) = make_float4(c[t][4] - lse, c[t][5] - lse, c[t][6] - lse, c[t][7] - lse);
    }
}

__global__ void k_hlast(const float* __restrict__ src, float* __restrict__ dst) {
    int idx = blockIdx.x * 256 + threadIdx.x;
    if (idx < B * H) dst[idx] = src[idx];
}

// ---------------- launch (single default stream, deterministic) ----------------
extern "C" void kernel_launch(void* const* d_in, const int* in_sizes, int n_in,
                              void* d_out, int out_size) {
    const float* enc    = (const float*)d_in[0];
    const float* hidden = (const float*)d_in[1];
    const int*   target = (const int*)d_in[2];
    const float* emb    = (const float*)d_in[3];
    const float* w_ih   = (const float*)d_in[4];
    const float* w_hh   = (const float*)d_in[5];
    const float* b_ih   = (const float*)d_in[6];
    const float* b_hh   = (const float*)d_in[7];
    const float* wa_w   = (const float*)d_in[8];
    const float* wa_b   = (const float*)d_in[9];
    const float* ua_w   = (const float*)d_in[10];
    const float* ua_b   = (const float*)d_in[11];
    const float* va_w   = (const float*)d_in[12];
    const float* va_b   = (const float*)d_in[13];
    float* out = (float*)d_out;

    float *xs, *gi, *ghp, *hs, *keys, *uk, *wq, *sc;
    cudaGetSymbolAddress((void**)&xs, g_xs);
    cudaGetSymbolAddress((void**)&gi, g_gi);
    cudaGetSymbolAddress((void**)&ghp, g_ghp);
    cudaGetSymbolAddress((void**)&hs, g_hs);
    cudaGetSymbolAddress((void**)&keys, g_keys);
    cudaGetSymbolAddress((void**)&uk, g_uk);
    cudaGetSymbolAddress((void**)&wq, g_wq);
    cudaGetSymbolAddress((void**)&sc, g_sc);

    // independent front work
    k_gather<<<(T * B * E + 255) / 256, 256>>>(target, emb, xs);
    k_keys<<<(B * S * H2 + 255) / 256, 256>>>(enc, keys);

    // uk = keys @ ua_w^T + ua_b [3200, 1024], K=2048 (largest GEMM)
    k_gemm_tf32<128, 128, 4, 2><<<dim3(H / 128, (B * S) / 128), 256>>>(
        keys, ua_w, ua_b, uk, B * S, H, H2, H2);

    // gi = xs @ w_ih^T + b_ih   [640, 3072], K=512
    k_gemm_tf32<128, 128, 4, 2><<<dim3(H3 / 128, (T * B) / 128), 256>>>(
        xs, w_ih, b_ih, gi, T * B, H3, E, E);

    // sequential GRU over T steps (split-K gh GEMM + fused reduce/gate)
    const float* hprev = hidden;  // [B, H]
    for (int t = 0; t < T; t++) {
        k_gemm_tf32<64, 128, 2, 4><<<dim3(H3 / 128, 1, KSPLIT), 256>>>(
            hprev, w_hh, nullptr, ghp, B, H3, H, H / KSPLIT);
        k_gru_red<<<(B * H + 255) / 256, 256>>>(ghp, gi + (size_t)t * B * H3, b_hh,
                                                hprev, hs + (size_t)t * B * H);
        hprev = hs + (size_t)t * B * H;
    }

    // wq = hs @ wa_w^T + wa_b   [640, 1024], K=1024
    k_gemm_tf32<128, 128, 4, 2><<<dim3(H / 128, (T * B) / 128), 256>>>(
        hs, wa_w, wa_b, wq, T * B, H, H, H);

    // additive attention scores + softmax
    k_scores<<<dim3(B, 4), 256>>>(wq, uk, va_w, va_b, sc);
    k_softmax<<<(T * B * 32 + 255) / 256, 256>>>(sc);

    // context + log_softmax into out[B, T, 2H]
    k_context<<<B, 256>>>(sc, keys, out);

    // h_last appended after out (tuple output flattened)
    if (out_size >= B * T * H2 + B * H)
        k_hlast<<<(B * H + 255) / 256, 256>>>(hs + (size_t)(T - 1) * B * H, out + B * T * H2);
}

// round 5
// speedup vs baseline: 4.5431x; 1.1384x over previous
#include <cuda_runtime.h>
#include <math.h>

// Problem dims (fixed by the reference)
namespace cfg {
constexpr int V = 32000, E = 512, H = 1024, S = 50, B = 64, T = 10;
constexpr int H2 = 2 * H, H3 = 3 * H;
constexpr int KSPLIT = 8;  // split-K factor for GRU gh GEMM
}
using namespace cfg;

// ---------------- device scratch (no allocations allowed) ----------------
__device__ float g_xs[T * B * E];          // gathered embeddings  [T*B, E]
__device__ float g_gi[T * B * H3];         // x @ w_ih^T + b_ih    [T*B, 3H]
__device__ float g_ghp[KSPLIT * B * H3];   // split-K partials of h @ w_hh^T
__device__ float g_hs[T * B * H];          // GRU hidden states    [T, B, H]
__device__ float g_uk[B * S * H];          // enc @ ua_w^T + ua_b, rows in (s*B+b) order
__device__ float g_wq[T * B * H];          // hs @ wa_w^T + wa_b   [T*B, H]
__device__ float g_sc[T * B * S];          // scores / weights     [T*B, S]

// ---------------- small intrinsics ----------------
__device__ __forceinline__ float tanha(float x) {
    float y;
    asm("tanh.approx.f32 %0, %1;" : "=f"(y) : "f"(x));
    return y;
}
__device__ __forceinline__ void mma8(float* c, const unsigned* a, const unsigned* b) {
    asm volatile(
        "mma.sync.aligned.m16n8k8.row.col.f32.tf32.tf32.f32 "
        "{%0,%1,%2,%3}, {%4,%5,%6,%7}, {%8,%9}, {%0,%1,%2,%3};"
        : "+f"(c[0]), "+f"(c[1]), "+f"(c[2]), "+f"(c[3])
        : "r"(a[0]), "r"(a[1]), "r"(a[2]), "r"(a[3]), "r"(b[0]), "r"(b[1]));
}
__device__ __forceinline__ void cp16(float* smem_dst, const float* gptr) {
    unsigned s = (unsigned)__cvta_generic_to_shared(smem_dst);
    asm volatile("cp.async.cg.shared.global [%0], [%1], 16;\n" :: "r"(s), "l"(gptr));
}

// ---------------- tf32 tensor-core GEMM (cp.async double-buffered) ---------
// C[m][n] = (bias?bias[n]:0) + sum_{k in [z*klen, z*klen+klen)} A[m][k]*W[n][k]
// A: [M,K] row-major, W: [N,K] row-major. blockIdx.z selects K split; output
// written to C + z*M*N. Requires M%BM==0, N%BN==0, klen%32==0.
// fp32 bits are fed to tf32 mma directly (truncation).
template <int BM, int BN, int WM, int WN>
__global__ void __launch_bounds__(WM * WN * 32)
k_gemm_tf32(const float* __restrict__ A, const float* __restrict__ W,
            const float* __restrict__ bias, float* __restrict__ C,
            int M, int N, int K, int klen) {
    constexpr int BK = 32;
    constexpr int NT = WM * WN * 32;      // threads per block
    constexpr int TM = BM / WM;           // warp tile M
    constexpr int TN = BN / WN;           // warp tile N
    constexpr int MM = TM / 16;           // mma tiles per warp (m)
    constexpr int MN = TN / 8;            // mma tiles per warp (n)
    constexpr int LDSR = BK + 4;          // pad -> conflict-free frag loads
    constexpr int A_LD = BM * (BK / 4) / NT;
    constexpr int B_LD = BN * (BK / 4) / NT;

    extern __shared__ float sm[];
    float* Asm = sm;                      // [2][BM*LDSR]
    float* Bsm = sm + 2 * BM * LDSR;      // [2][BN*LDSR]

    const int tid = threadIdx.x;
    const int warp = tid >> 5, lane = tid & 31;
    const int wm = warp / WN, wn = warp % WN;
    const int g = lane >> 2, tg = lane & 3;
    const int bm = blockIdx.y * BM, bn = blockIdx.x * BN;
    const int kstart = blockIdx.z * klen;
    C += (size_t)blockIdx.z * M * N;

    float acc[MM][MN][4];
#pragma unroll
    for (int im = 0; im < MM; im++)
#pragma unroll
        for (int in = 0; in < MN; in++)
#pragma unroll
            for (int q = 0; q < 4; q++) acc[im][in][q] = 0.f;

    auto issue = [&](int k0, int buf) {
        float* as = Asm + buf * BM * LDSR;
        float* bs = Bsm + buf * BN * LDSR;
#pragma unroll
        for (int i = 0; i < A_LD; i++) {
            int idx = tid + i * NT;
            int r = idx >> 3, kq = idx & 7;
            cp16(&as[r * LDSR + kq * 4],
                 A + (size_t)(bm + r) * K + kstart + k0 + kq * 4);
        }
#pragma unroll
        for (int i = 0; i < B_LD; i++) {
            int idx = tid + i * NT;
            int r = idx >> 3, kq = idx & 7;
            cp16(&bs[r * LDSR + kq * 4],
                 W + (size_t)(bn + r) * K + kstart + k0 + kq * 4);
        }
        asm volatile("cp.async.commit_group;\n" ::);
    };

    issue(0, 0);
    const int KT = klen / BK;
    for (int kt = 0; kt < KT; kt++) {
        if (kt + 1 < KT) {
            issue((kt + 1) * BK, (kt + 1) & 1);
            asm volatile("cp.async.wait_group 1;\n" ::);   // buffer kt ready
        } else {
            asm volatile("cp.async.wait_group 0;\n" ::);
        }
        __syncthreads();

        const float* as = Asm + (kt & 1) * BM * LDSR;
        const float* bs = Bsm + (kt & 1) * BN * LDSR;
#pragma unroll
        for (int ks = 0; ks < 4; ks++) {
            const int kk = ks * 8;
            unsigned af[MM][4], bf[MN][2];
#pragma unroll
            for (int im = 0; im < MM; im++) {
                int m0 = wm * TM + im * 16;
                af[im][0] = __float_as_uint(as[(m0 + g) * LDSR + kk + tg]);
                af[im][1] = __float_as_uint(as[(m0 + 8 + g) * LDSR + kk + tg]);
                af[im][2] = __float_as_uint(as[(m0 + g) * LDSR + kk + 4 + tg]);
                af[im][3] = __float_as_uint(as[(m0 + 8 + g) * LDSR + kk + 4 + tg]);
            }
#pragma unroll
            for (int in = 0; in < MN; in++) {
                int n0 = wn * TN + in * 8;
                bf[in][0] = __float_as_uint(bs[(n0 + g) * LDSR + kk + tg]);
                bf[in][1] = __float_as_uint(bs[(n0 + g) * LDSR + kk + 4 + tg]);
            }
#pragma unroll
            for (int im = 0; im < MM; im++)
#pragma unroll
                for (int in = 0; in < MN; in++)
                    mma8(acc[im][in], af[im], bf[in]);
        }
        __syncthreads();
    }

    // epilogue: + bias (optional), write
#pragma unroll
    for (int im = 0; im < MM; im++) {
        int row0 = bm + wm * TM + im * 16 + g;
#pragma unroll
        for (int in = 0; in < MN; in++) {
            int col = bn + wn * TN + in * 8 + 2 * tg;
            float bx = 0.f, by = 0.f;
            if (bias) {
                float2 bb = *(const float2*)(bias + col);
                bx = bb.x; by = bb.y;
            }
            float* c = acc[im][in];
            *(float2*)(C + (size_t)row0 * N + col) = make_float2(c[0] + bx, c[1] + by);
            *(float2*)(C + (size_t)(row0 + 8) * N + col) = make_float2(c[2] + bx, c[3] + by);
        }
    }
}

// ---------------- elementwise / attention kernels ----------------

__global__ void k_gather(const int* __restrict__ target,
                         const float* __restrict__ emb,
                         float* __restrict__ xs) {
    int idx = blockIdx.x * 256 + threadIdx.x;
    if (idx >= T * B * E) return;
    int e = idx % E;
    int m = idx / E;
    int b = m % B;
    int t = m / B;
    int tok = (t == 0) ? 0 : target[b * T + (t - 1)];
    xs[idx] = emb[tok * E + e];
}

// reduce split-K partials of gh, add biases, apply GRU gates (accurate math).
__global__ void k_gru_red(const float* __restrict__ part, const float* __restrict__ gi,
                          const float* __restrict__ b_hh_, const float* __restrict__ hprev,
                          float* __restrict__ hnew) {
    int idx = blockIdx.x * 256 + threadIdx.x;
    if (idx >= B * H) return;
    int b = idx / H, j = idx % H;
    float hr = b_hh_[j], hz = b_hh_[H + j], hn = b_hh_[2 * H + j];
#pragma unroll
    for (int s = 0; s < KSPLIT; s++) {
        const float* p = part + (size_t)s * B * H3 + (size_t)b * H3;
        hr += p[j];
        hz += p[H + j];
        hn += p[2 * H + j];
    }
    const float* gib = gi + (size_t)b * H3;
    float ir = gib[j], iz = gib[H + j], in_ = gib[2 * H + j];
    float r = 1.f / (1.f + expf(-(ir + hr)));
    float z = 1.f / (1.f + expf(-(iz + hz)));
    float n = tanhf(in_ + r * hn);
    hnew[idx] = (1.f - z) * n + z * hprev[idx];
}

// scores: grid (B, 4); wq[T][H] staged in smem; uk rows are in (s*B+b) order.
__global__ void k_scores(const float* __restrict__ wq, const float* __restrict__ uk,
                         const float* __restrict__ va_w, const float* __restrict__ va_b,
                         float* __restrict__ scores) {
    __shared__ float wqs[T][H];  // 40 KB
    int b = blockIdx.x, q = blockIdx.y;
    int tid = threadIdx.x;
    for (int i = tid; i < T * H; i += 256) {
        wqs[0][i] = wq[(size_t)(i / H * B + b) * H + (i % H)];
    }
    __syncthreads();

    int warp = tid >> 5, lane = tid & 31;
    float vb = va_b[0];
    for (int s = q * 8 + warp; s < S; s += 32) {
        const float4* ukr = (const float4*)(uk + (size_t)(s * B + b) * H);
        const float4* vw = (const float4*)va_w;
        float acc[T];
#pragma unroll
        for (int t = 0; t < T; t++) acc[t] = 0.f;
#pragma unroll
        for (int i = 0; i < H / 128; i++) {
            float4 u = ukr[lane + i * 32];
            float4 v = vw[lane + i * 32];
#pragma unroll
            for (int t = 0; t < T; t++) {
                float4 w = *(const float4*)&wqs[t][(lane + i * 32) * 4];
                float a = acc[t];
                a = fmaf(v.x, tanha(w.x + u.x), a);
                a = fmaf(v.y, tanha(w.y + u.y), a);
                a = fmaf(v.z, tanha(w.z + u.z), a);
                a = fmaf(v.w, tanha(w.w + u.w), a);
                acc[t] = a;
            }
        }
#pragma unroll
        for (int t = 0; t < T; t++) {
#pragma unroll
            for (int o = 16; o; o >>= 1) acc[t] += __shfl_xor_sync(0xffffffffu, acc[t], o);
            if (lane == 0) scores[(size_t)(t * B + b) * S + s] = acc[t] + vb;
        }
    }
}

// softmax over S (=50) per row; one warp per (t,b)
__global__ void k_softmax(float* __restrict__ scores) {
    int row = (blockIdx.x * blockDim.x + threadIdx.x) >> 5;
    int lane = threadIdx.x & 31;
    if (row >= T * B) return;
    float* p = scores + (size_t)row * S;
    float v0 = (lane < S) ? p[lane] : -1e30f;
    float v1 = (lane + 32 < S) ? p[lane + 32] : -1e30f;
    float m = fmaxf(v0, v1);
#pragma unroll
    for (int o = 16; o; o >>= 1) m = fmaxf(m, __shfl_xor_sync(0xffffffffu, m, o));
    float e0 = (lane < S) ? expf(v0 - m) : 0.f;
    float e1 = (lane + 32 < S) ? expf(v1 - m) : 0.f;
    float sum = e0 + e1;
#pragma unroll
    for (int o = 16; o; o >>= 1) sum += __shfl_xor_sync(0xffffffffu, sum, o);
    float inv = 1.f / sum;
    if (lane < S) p[lane] = e0 * inv;
    if (lane + 32 < S) p[lane + 32] = e1 * inv;
}

// context + log_softmax: one block per b; enc rows (s*B+b) streamed once for all T.
__global__ void k_context(const float* __restrict__ weights,
                          const float* __restrict__ enc,
                          float* __restrict__ out) {
    int b = blockIdx.x;
    int tid = threadIdx.x;
    __shared__ float w[T][S];
    __shared__ float red[8];

    for (int i = tid; i < T * S; i += 256) {
        int t = i / S, s = i % S;
        w[t][s] = weights[(size_t)(t * B + b) * S + s];
    }
    __syncthreads();

    float c[T][8];
#pragma unroll
    for (int t = 0; t < T; t++)
#pragma unroll
        for (int i = 0; i < 8; i++) c[t][i] = 0.f;

    for (int s = 0; s < S; s++) {
        const float* kr = enc + (size_t)(s * B + b) * H2;
        float4 k0 = *(const float4*)(kr + tid * 8);
        float4 k1 = *(const float4*)(kr + tid * 8 + 4);
        float kv[8] = {k0.x, k0.y, k0.z, k0.w, k1.x, k1.y, k1.z, k1.w};
#pragma unroll
        for (int t = 0; t < T; t++) {
            float ws = w[t][s];
#pragma unroll
            for (int i = 0; i < 8; i++) c[t][i] = fmaf(ws, kv[i], c[t][i]);
        }
    }

    for (int t = 0; t < T; t++) {
        float m = c[t][0];
#pragma unroll
        for (int i = 1; i < 8; i++) m = fmaxf(m, c[t][i]);
#pragma unroll
        for (int o = 16; o; o >>= 1) m = fmaxf(m, __shfl_xor_sync(0xffffffffu, m, o));
        if ((tid & 31) == 0) red[tid >> 5] = m;
        __syncthreads();
        if (tid == 0) {
            float mm = red[0];
            for (int i = 1; i < 8; i++) mm = fmaxf(mm, red[i]);
            red[0] = mm;
        }
        __syncthreads();
        m = red[0];
        __syncthreads();

        float sum = 0.f;
#pragma unroll
        for (int i = 0; i < 8; i++) sum += expf(c[t][i] - m);
#pragma unroll
        for (int o = 16; o; o >>= 1) sum += __shfl_xor_sync(0xffffffffu, sum, o);
        if ((tid & 31) == 0) red[tid >> 5] = sum;
        __syncthreads();
        if (tid == 0) {
            float ss = 0.f;
            for (int i = 1; i < 8; i++) ss += red[i];
            red[0] += ss;
        }
        __syncthreads();
        float lse = m + logf(red[0]);
        __syncthreads();

        float* o_ = out + (size_t)(b * T + t) * H2 + tid * 8;
        *(float4*)o_ = make_float4(c[t][0] - lse, c[t][1] - lse, c[t][2] - lse, c[t][3] - lse);
        *(float4*)(o_ + 4) = make_float4(c[t][4] - lse, c[t][5] - lse, c[t][6] - lse, c[t][7] - lse);
    }
}

__global__ void k_hlast(const float* __restrict__ src, float* __restrict__ dst) {
    int idx = blockIdx.x * 256 + threadIdx.x;
    if (idx < B * H) dst[idx] = src[idx];
}

// ---------------- launch (single default stream, deterministic) -------------
extern "C" void kernel_launch(void* const* d_in, const int* in_sizes, int n_in,
                              void* d_out, int out_size) {
    const float* enc    = (const float*)d_in[0];
    const float* hidden = (const float*)d_in[1];
    const int*   target = (const int*)d_in[2];
    const float* emb    = (const float*)d_in[3];
    const float* w_ih   = (const float*)d_in[4];
    const float* w_hh   = (const float*)d_in[5];
    const float* b_ih   = (const float*)d_in[6];
    const float* b_hh   = (const float*)d_in[7];
    const float* wa_w   = (const float*)d_in[8];
    const float* wa_b   = (const float*)d_in[9];
    const float* ua_w   = (const float*)d_in[10];
    const float* ua_b   = (const float*)d_in[11];
    const float* va_w   = (const float*)d_in[12];
    const float* va_b   = (const float*)d_in[13];
    float* out = (float*)d_out;

    float *xs, *gi, *ghp, *hs, *uk, *wq, *sc;
    cudaGetSymbolAddress((void**)&xs, g_xs);
    cudaGetSymbolAddress((void**)&gi, g_gi);
    cudaGetSymbolAddress((void**)&ghp, g_ghp);
    cudaGetSymbolAddress((void**)&hs, g_hs);
    cudaGetSymbolAddress((void**)&uk, g_uk);
    cudaGetSymbolAddress((void**)&wq, g_wq);
    cudaGetSymbolAddress((void**)&sc, g_sc);

    // dynamic smem (double-buffered): 2*(BM+BN)*36*4 bytes
    constexpr int LDSR = 36;
    const int smem_big = 2 * (128 + 128) * LDSR * 4;   // 73728 B
    const int smem_gh  = 2 * (64 + 128) * LDSR * 4;    // 55296 B
    cudaFuncSetAttribute(k_gemm_tf32<128, 128, 4, 2>,
                         cudaFuncAttributeMaxDynamicSharedMemorySize, smem_big);
    cudaFuncSetAttribute(k_gemm_tf32<64, 128, 2, 4>,
                         cudaFuncAttributeMaxDynamicSharedMemorySize, smem_gh);

    // independent front work
    k_gather<<<(T * B * E + 255) / 256, 256>>>(target, emb, xs);

    // uk = enc @ ua_w^T + ua_b  [3200, 1024], K=2048; rows in natural (s*B+b) order
    k_gemm_tf32<128, 128, 4, 2><<<dim3(H / 128, (B * S) / 128), 256, smem_big>>>(
        enc, ua_w, ua_b, uk, B * S, H, H2, H2);

    // gi = xs @ w_ih^T + b_ih   [640, 3072], K=512
    k_gemm_tf32<128, 128, 4, 2><<<dim3(H3 / 128, (T * B) / 128), 256, smem_big>>>(
        xs, w_ih, b_ih, gi, T * B, H3, E, E);

    // sequential GRU over T steps (split-K gh GEMM + fused reduce/gate)
    const float* hprev = hidden;  // [B, H]
    for (int t = 0; t < T; t++) {
        k_gemm_tf32<64, 128, 2, 4><<<dim3(H3 / 128, 1, KSPLIT), 256, smem_gh>>>(
            hprev, w_hh, nullptr, ghp, B, H3, H, H / KSPLIT);
        k_gru_red<<<(B * H + 255) / 256, 256>>>(ghp, gi + (size_t)t * B * H3, b_hh,
                                                hprev, hs + (size_t)t * B * H);
        hprev = hs + (size_t)t * B * H;
    }

    // wq = hs @ wa_w^T + wa_b   [640, 1024], K=1024
    k_gemm_tf32<128, 128, 4, 2><<<dim3(H / 128, (T * B) / 128), 256, smem_big>>>(
        hs, wa_w, wa_b, wq, T * B, H, H, H);

    // additive attention scores + softmax
    k_scores<<<dim3(B, 4), 256>>>(wq, uk, va_w, va_b, sc);
    k_softmax<<<(T * B * 32 + 255) / 256, 256>>>(sc);

    // context + log_softmax into out[B, T, 2H] (reads enc directly)
    k_context<<<B, 256>>>(sc, enc, out);

    // h_last appended after out (tuple output flattened)
    if (out_size >= B * T * H2 + B * H)
        k_hlast<<<(B * H + 255) / 256, 256>>>(hs + (size_t)(T - 1) * B * H, out + B * T * H2);
}